// round 12
// baseline (speedup 1.0000x reference)
#include <cuda_runtime.h>
#include <cuda_bf16.h>
#include <cstdint>
#include <cstddef>

#define BSZ 4
#define SEQ 4096
#define DM  2048
#define NH  16
#define DH  128
#define MROWS (BSZ*SEQ)               // 16384
#define OUT_ELEMS ((size_t)MROWS*DM)  // 33554432
#define STATE_ELEMS ((size_t)BSZ*NH*DH*DH)
#define QSCALE 0.08838834764831845f   // 1/sqrt(128)
#define TAU 2.5e-4f                   // sign-ambiguity threshold
#define CAND_CAP 262144

typedef unsigned long long u64;

// ---------------- scratch (device globals: allocation-free rule) ------------
__device__ float  g_q [(size_t)MROWS*DM];
__device__ int8_t g_k [(size_t)MROWS*DM];
__device__ int8_t g_v [(size_t)MROWS*DM];
__device__ __nv_bfloat16 g_x1[(size_t)MROWS*DM];
__device__ __nv_bfloat16 g_x2[(size_t)MROWS*DM];
__device__ __nv_bfloat16 g_a1[(size_t)MROWS*DM];
__device__ __nv_bfloat16 g_a2[(size_t)MROWS*DM];
__device__ __nv_bfloat16 g_wq1[(size_t)DM*DM];
__device__ __nv_bfloat16 g_wq2[(size_t)DM*DM];
__device__ __nv_bfloat16 g_wk1[(size_t)DM*DM];
__device__ __nv_bfloat16 g_wk2[(size_t)DM*DM];
__device__ __nv_bfloat16 g_wv1[(size_t)DM*DM];
__device__ __nv_bfloat16 g_wv2[(size_t)DM*DM];
__device__ __nv_bfloat16 g_wo1[(size_t)DM*DM];
__device__ __nv_bfloat16 g_wo2[(size_t)DM*DM];
__device__ uint32_t g_cand[CAND_CAP];
__device__ uint32_t g_ncand;

// ---------------- mma.sync / ldmatrix / cp.async helpers --------------------
__device__ __forceinline__ uint32_t smem_u32(const void* p) {
    uint32_t a;
    asm("{ .reg .u64 t; cvta.to.shared.u64 t, %1; cvt.u32.u64 %0, t; }"
        : "=r"(a) : "l"(p));
    return a;
}
__device__ __forceinline__ void ldsm4(uint32_t* r, uint32_t addr) {
    asm volatile("ldmatrix.sync.aligned.m8n8.x4.shared.b16 {%0,%1,%2,%3}, [%4];"
        : "=r"(r[0]), "=r"(r[1]), "=r"(r[2]), "=r"(r[3]) : "r"(addr));
}
__device__ __forceinline__ void mma_bf16(float* c, const uint32_t* a,
                                         const uint32_t* b) {
    asm volatile(
        "mma.sync.aligned.m16n8k16.row.col.f32.bf16.bf16.f32 "
        "{%0,%1,%2,%3}, {%4,%5,%6,%7}, {%8,%9}, {%0,%1,%2,%3};"
        : "+f"(c[0]), "+f"(c[1]), "+f"(c[2]), "+f"(c[3])
        : "r"(a[0]), "r"(a[1]), "r"(a[2]), "r"(a[3]), "r"(b[0]), "r"(b[1]));
}
#define CPA(dst, src) asm volatile("cp.async.cg.shared.global [%0], [%1], 16;" :: "r"(dst), "l"(src))
#define CPC()         asm volatile("cp.async.commit_group;")
#define CPW2()        asm volatile("cp.async.wait_group 2;")

// ---------------------------------------------------------------------------
// split: fp32 -> bf16 hi + bf16 lo
// ---------------------------------------------------------------------------
__global__ void split_bf16(const float* __restrict__ s, size_t n,
                           __nv_bfloat16* __restrict__ hi,
                           __nv_bfloat16* __restrict__ lo)
{
    size_t stride = (size_t)gridDim.x * blockDim.x * 4;
    for (size_t i = ((size_t)blockIdx.x * blockDim.x + threadIdx.x) * 4;
         i < n; i += stride) {
        float4 v = *(const float4*)(s + i);
        __nv_bfloat16 hx = __float2bfloat16(v.x);
        __nv_bfloat16 hy = __float2bfloat16(v.y);
        __nv_bfloat16 hz = __float2bfloat16(v.z);
        __nv_bfloat16 hw = __float2bfloat16(v.w);
        __nv_bfloat16 lx = __float2bfloat16(v.x - __bfloat162float(hx));
        __nv_bfloat16 ly = __float2bfloat16(v.y - __bfloat162float(hy));
        __nv_bfloat16 lz = __float2bfloat16(v.z - __bfloat162float(hz));
        __nv_bfloat16 lw = __float2bfloat16(v.w - __bfloat162float(hw));
        *(__nv_bfloat162*)(hi + i)     = __nv_bfloat162(hx, hy);
        *(__nv_bfloat162*)(hi + i + 2) = __nv_bfloat162(hz, hw);
        *(__nv_bfloat162*)(lo + i)     = __nv_bfloat162(lx, ly);
        *(__nv_bfloat162*)(lo + i + 2) = __nv_bfloat162(lz, lw);
    }
}

__global__ void zero_cnt() { g_ncand = 0; }

// ---------------------------------------------------------------------------
// 2-split bf16 mma GEMM (NT), 4-stage cp.async ring:
//   C = A@B^T via A1B1 + A1B2 + A2B1, fp32 register accumulators.
// Compute/accumulation order identical to the validated 2-stage kernel ->
// bit-identical outputs; only prefetch depth differs.
// MODE 0: fp32 out.  MODE 1: fp32 out * QSCALE.
// MODE 2: int8 sign out + ambiguity candidates (|v| < TAU -> list).
// ---------------------------------------------------------------------------
#define RS   40
#define TILE_B (128 * RS * 2)          // 10240
#define BUF_B  (4 * TILE_B)            // 40960
#define MMA4_SMEM (4 * BUF_B)          // 163840

template<int MODE>
__global__ void __launch_bounds__(256, 1)
mmah_gemm4(const __nv_bfloat16* __restrict__ A1, const __nv_bfloat16* __restrict__ A2,
           const __nv_bfloat16* __restrict__ B1, const __nv_bfloat16* __restrict__ B2,
           void* __restrict__ Cv, uint32_t tag)
{
    extern __shared__ char sm[];
    const uint32_t smb = smem_u32(sm);
    const int tid = threadIdx.x, lane = tid & 31, w = tid >> 5;
    const int m0 = blockIdx.y * 128, n0 = blockIdx.x * 128;
    const int wm = (w & 3) * 32, wn = (w >> 2) * 64;

    const __nv_bfloat16* src[4] = {A1, A2, B1, B2};
    const int rbs[4] = {m0, m0, n0, n0};
    constexpr int NT = DM / 32;   // 64 stages

    auto issue = [&](int t) {
        const uint32_t bb = smb + (uint32_t)(t & 3) * BUF_B;
        const int k0 = t * 32;
#pragma unroll
        for (int i = 0; i < 2; i++) {
            const int c = tid + 256 * i;
            const int row = c >> 2, col8 = (c & 3) * 8;
#pragma unroll
            for (int X = 0; X < 4; X++) {
                uint32_t dst = bb + (uint32_t)X * TILE_B + row * (RS * 2) + col8 * 2;
                const __nv_bfloat16* s = src[X] + (size_t)(rbs[X] + row) * DM + k0 + col8;
                CPA(dst, s);
            }
        }
    };

    float acc[2][8][4];
#pragma unroll
    for (int mt = 0; mt < 2; mt++)
#pragma unroll
        for (int nt = 0; nt < 8; nt++)
#pragma unroll
            for (int e = 0; e < 4; e++) acc[mt][nt][e] = 0.f;

    issue(0); CPC(); issue(1); CPC(); issue(2); CPC();

    const int arow = wm + (lane & 15);
    const uint32_t acolo = ((lane >> 4) << 3) * 2;
    const int brow = wn + (lane & 7) + ((lane >> 4) << 3);
    const uint32_t bcolo = (((lane >> 3) & 1) << 3) * 2;

    for (int t = 0; t < NT; t++) {
        CPW2();                 // stage t's group complete (<=2 younger pending)
        __syncthreads();        // all warps past compute(t-1); ring slot safe
        if (t + 3 < NT) { issue(t + 3); CPC(); }

        const uint32_t bb = smb + (uint32_t)(t & 3) * BUF_B;
#pragma unroll
        for (int ks = 0; ks < 32; ks += 16) {
            const uint32_t ko = (uint32_t)ks * 2;
            uint32_t a1f[2][4], a2f[2][4], b1f[8][2], b2f[8][2];
            ldsm4(a1f[0], bb + 0*TILE_B + (arow     ) * (RS*2) + ko + acolo);
            ldsm4(a1f[1], bb + 0*TILE_B + (arow + 16) * (RS*2) + ko + acolo);
            ldsm4(a2f[0], bb + 1*TILE_B + (arow     ) * (RS*2) + ko + acolo);
            ldsm4(a2f[1], bb + 1*TILE_B + (arow + 16) * (RS*2) + ko + acolo);
#pragma unroll
            for (int np = 0; np < 4; np++) {
                uint32_t r[4];
                ldsm4(r, bb + 2*TILE_B + (brow + np*16) * (RS*2) + ko + bcolo);
                b1f[np*2][0] = r[0]; b1f[np*2][1] = r[1];
                b1f[np*2+1][0] = r[2]; b1f[np*2+1][1] = r[3];
                ldsm4(r, bb + 3*TILE_B + (brow + np*16) * (RS*2) + ko + bcolo);
                b2f[np*2][0] = r[0]; b2f[np*2][1] = r[1];
                b2f[np*2+1][0] = r[2]; b2f[np*2+1][1] = r[3];
            }
#pragma unroll
            for (int mt = 0; mt < 2; mt++)
#pragma unroll
                for (int nt = 0; nt < 8; nt++) {
                    mma_bf16(acc[mt][nt], a1f[mt], b1f[nt]);
                    mma_bf16(acc[mt][nt], a1f[mt], b2f[nt]);
                    mma_bf16(acc[mt][nt], a2f[mt], b1f[nt]);
                }
        }
    }

    if (MODE == 2) {
        int8_t* Cs = (int8_t*)Cv;
#pragma unroll
        for (int mt = 0; mt < 2; mt++)
#pragma unroll
            for (int nt = 0; nt < 8; nt++) {
                const int m = m0 + wm + mt * 16 + (lane >> 2);
                const int n = n0 + wn + nt * 8 + 2 * (lane & 3);
                const float* a = acc[mt][nt];
                char2 c01 = {(char)((a[0] >= 0.f) ? 1 : -1),
                             (char)((a[1] >= 0.f) ? 1 : -1)};
                char2 c23 = {(char)((a[2] >= 0.f) ? 1 : -1),
                             (char)((a[3] >= 0.f) ? 1 : -1)};
                *(char2*)&Cs[(size_t)m * DM + n]       = c01;
                *(char2*)&Cs[(size_t)(m + 8) * DM + n] = c23;
                const int mm[4] = {m, m, m + 8, m + 8};
                const int nn[4] = {n, n + 1, n, n + 1};
#pragma unroll
                for (int e = 0; e < 4; e++) {
                    if (fabsf(a[e]) < TAU) {
                        uint32_t idx = atomicAdd(&g_ncand, 1u);
                        if (idx < CAND_CAP)
                            g_cand[idx] = (tag << 25) |
                                          ((uint32_t)mm[e] << 11) | (uint32_t)nn[e];
                    }
                }
            }
    } else {
        float* C = (float*)Cv;
        const float s = (MODE == 1) ? QSCALE : 1.0f;
#pragma unroll
        for (int mt = 0; mt < 2; mt++)
#pragma unroll
            for (int nt = 0; nt < 8; nt++) {
                const int m = m0 + wm + mt * 16 + (lane >> 2);
                const int n = n0 + wn + nt * 8 + 2 * (lane & 3);
                float2 o0 = {acc[mt][nt][0] * s, acc[mt][nt][1] * s};
                float2 o1 = {acc[mt][nt][2] * s, acc[mt][nt][3] * s};
                *(float2*)&C[(size_t)m * DM + n]       = o0;
                *(float2*)&C[(size_t)(m + 8) * DM + n] = o1;
            }
    }
}

// ---------------------------------------------------------------------------
// Fixup: recompute each ambiguous element with the EXACT arithmetic of the
// validated fp32 gemm path: 32 segments of 64 sequential fmaf (k ascending),
// acc += segment. Signs bit-identical to the validated kernel.
// ---------------------------------------------------------------------------
__global__ void __launch_bounds__(256)
fixup(const float* __restrict__ x, const float* __restrict__ Wk,
      const float* __restrict__ Wv)
{
    uint32_t ncand = g_ncand;
    if (ncand > CAND_CAP) ncand = CAND_CAP;
    const uint32_t total = gridDim.x * blockDim.x;
    for (uint32_t i = blockIdx.x * blockDim.x + threadIdx.x; i < ncand;
         i += total) {
        const uint32_t c = g_cand[i];
        const int col = c & 2047;
        const int m   = (c >> 11) & 16383;
        const int tag = c >> 25;
        const float* a = x + (size_t)m * DM;
        const float* b = (tag ? Wv : Wk) + (size_t)col * DM;
        float acc = 0.f;
        for (int s = 0; s < 32; s++) {
            float tmp = 0.f;
            const float* as = a + s * 64;
            const float* bs = b + s * 64;
#pragma unroll
            for (int k4 = 0; k4 < 64; k4 += 4) {
                float4 av = *(const float4*)(as + k4);
                float4 bv = *(const float4*)(bs + k4);
                tmp = fmaf(av.x, bv.x, tmp);
                tmp = fmaf(av.y, bv.y, tmp);
                tmp = fmaf(av.z, bv.z, tmp);
                tmp = fmaf(av.w, bv.w, tmp);
            }
            acc += tmp;
        }
        int8_t* dst = tag ? g_v : g_k;
        dst[(size_t)m * DM + col] = (acc >= 0.f) ? (int8_t)1 : (int8_t)-1;
    }
}

// ---------------------------------------------------------------------------
// Attention scan (validated; epilogue writes bf16 2-split of output).
// ---------------------------------------------------------------------------
struct AttSmem {
    float  qcT[128][132];
    float  scoresT[128][132];
    float  state[128][68];
    int8_t kc[128][144];
    int8_t kT[128][144];
    int8_t vc[128][80];
};

__device__ __forceinline__ void b4_to_f(unsigned w, float* f) {
    f[0] = (float)((int)(w << 24) >> 24);
    f[1] = (float)((int)(w << 16) >> 24);
    f[2] = (float)((int)(w <<  8) >> 24);
    f[3] = (float)((int) w        >> 24);
}

__global__ void __launch_bounds__(256)
att_kernel(const float* __restrict__ gq, const int8_t* __restrict__ gk,
           const int8_t* __restrict__ gv,
           __nv_bfloat16* __restrict__ ga1, __nv_bfloat16* __restrict__ ga2,
           float* __restrict__ gstate, int write_state)
{
    extern __shared__ char sraw[];
    AttSmem& S = *(AttSmem*)sraw;

    const int pair = blockIdx.x;
    const int half = pair & 1;
    const int bh   = pair >> 1;
    const int b    = bh >> 4, h = bh & 15;
    const int tid  = threadIdx.x;

    for (int i = tid; i < 128 * 68; i += 256)
        ((float*)S.state)[i] = 0.f;

    const int ty = tid >> 4, tx = tid & 15;
    const int i0 = ty * 8, j0 = tx * 8, e0 = tx * 4;

    const size_t base_row = (size_t)b * SEQ;
    const int colq = h * DH;
    const int colv = h * DH + half * 64;

    const int lc = tid >> 1;
    const int dh = (tid & 1) * 64;

    for (int n = 0; n < 32; n++) {
        {
            const size_t row = base_row + (size_t)n * 128 + lc;
            const float* qs = gq + row * DM + colq + dh;
#pragma unroll
            for (int d4 = 0; d4 < 64; d4 += 4) {
                float4 v = *(const float4*)(qs + d4);
                S.qcT[dh + d4 + 0][lc] = v.x;
                S.qcT[dh + d4 + 1][lc] = v.y;
                S.qcT[dh + d4 + 2][lc] = v.z;
                S.qcT[dh + d4 + 3][lc] = v.w;
            }
            const int8_t* ks = gk + row * DM + colq + dh;
#pragma unroll
            for (int d16 = 0; d16 < 64; d16 += 16) {
                int4 kw = *(const int4*)(ks + d16);
                *(int4*)&S.kc[lc][dh + d16] = kw;
                const int8_t* kb = (const int8_t*)&kw;
#pragma unroll
                for (int z = 0; z < 16; z++)
                    S.kT[dh + d16 + z][lc] = kb[z];
            }
            const int8_t* vs = gv + row * DM + colv + (dh >> 1);
            *(int4*)&S.vc[lc][(dh >> 1) + 0]  = *(const int4*)(vs);
            *(int4*)&S.vc[lc][(dh >> 1) + 16] = *(const int4*)(vs + 16);
        }
        __syncthreads();

        float sc[8][8], cr[8][4];
#pragma unroll
        for (int i = 0; i < 8; i++) {
#pragma unroll
            for (int j = 0; j < 8; j++) sc[i][j] = 0.f;
#pragma unroll
            for (int e = 0; e < 4; e++) cr[i][e] = 0.f;
        }
        for (int kk = 0; kk < 128; kk++) {
            float4 q0 = *(const float4*)&S.qcT[kk][i0];
            float4 q1 = *(const float4*)&S.qcT[kk][i0 + 4];
            float qv[8] = {q0.x, q0.y, q0.z, q0.w, q1.x, q1.y, q1.z, q1.w};
            uint2 kw = *(const uint2*)&S.kT[kk][j0];
            float kf[8];
            b4_to_f(kw.x, kf); b4_to_f(kw.y, kf + 4);
            float4 st = *(const float4*)&S.state[kk][e0];
            float sf[4] = {st.x, st.y, st.z, st.w};
#pragma unroll
            for (int i = 0; i < 8; i++) {
#pragma unroll
                for (int j = 0; j < 8; j++)
                    sc[i][j] = fmaf(qv[i], kf[j], sc[i][j]);
#pragma unroll
                for (int e = 0; e < 4; e++)
                    cr[i][e] = fmaf(qv[i], sf[e], cr[i][e]);
            }
        }
#pragma unroll
        for (int jj = 0; jj < 8; jj++)
#pragma unroll
            for (int ii = 0; ii < 8; ii++) {
                int gi = i0 + ii, gj = j0 + jj;
                S.scoresT[gj][gi] = (gj <= gi) ? sc[ii][jj] : 0.f;
            }
        __syncthreads();

        float in8[8][4], up[8][4];
#pragma unroll
        for (int i = 0; i < 8; i++)
#pragma unroll
            for (int e = 0; e < 4; e++) { in8[i][e] = 0.f; up[i][e] = 0.f; }

        for (int kk = 0; kk < 128; kk++) {
            float4 s0 = *(const float4*)&S.scoresT[kk][i0];
            float4 s1 = *(const float4*)&S.scoresT[kk][i0 + 4];
            float sv[8] = {s0.x, s0.y, s0.z, s0.w, s1.x, s1.y, s1.z, s1.w};
            uint2 kw = *(const uint2*)&S.kc[kk][i0];
            float kf[8];
            b4_to_f(kw.x, kf); b4_to_f(kw.y, kf + 4);
            unsigned vw = *(const unsigned*)&S.vc[kk][e0];
            float vf[4];
            b4_to_f(vw, vf);
#pragma unroll
            for (int i = 0; i < 8; i++)
#pragma unroll
                for (int e = 0; e < 4; e++) {
                    in8[i][e] = fmaf(sv[i], vf[e], in8[i][e]);
                    up[i][e]  = fmaf(kf[i], vf[e], up[i][e]);
                }
        }
#pragma unroll
        for (int ii = 0; ii < 8; ii++) {
            size_t row = (base_row + (size_t)n * 128 + i0 + ii) * DM + colv + e0;
            float o[4] = {cr[ii][0] + in8[ii][0], cr[ii][1] + in8[ii][1],
                          cr[ii][2] + in8[ii][2], cr[ii][3] + in8[ii][3]};
            __nv_bfloat16 hb[4], lb[4];
#pragma unroll
            for (int e = 0; e < 4; e++) {
                hb[e] = __float2bfloat16(o[e]);
                lb[e] = __float2bfloat16(o[e] - __bfloat162float(hb[e]));
            }
            *(__nv_bfloat162*)(ga1 + row)     = __nv_bfloat162(hb[0], hb[1]);
            *(__nv_bfloat162*)(ga1 + row + 2) = __nv_bfloat162(hb[2], hb[3]);
            *(__nv_bfloat162*)(ga2 + row)     = __nv_bfloat162(lb[0], lb[1]);
            *(__nv_bfloat162*)(ga2 + row + 2) = __nv_bfloat162(lb[2], lb[3]);
#pragma unroll
            for (int e = 0; e < 4; e++)
                S.state[i0 + ii][e0 + e] += up[ii][e];
        }
        __syncthreads();
    }

    if (write_state) {
        for (int idx = tid; idx < 128 * 64; idx += 256) {
            int d = idx >> 6, e = idx & 63;
            gstate[(((size_t)(b * NH + h) * DH) + d) * DH + half * 64 + e]
                = S.state[d][e];
        }
    }
}

// ---------------------------------------------------------------------------
extern "C" void kernel_launch(void* const* d_in, const int* in_sizes, int n_in,
                              void* d_out, int out_size)
{
    const float* x  = (const float*)d_in[0];
    const float* Wq = (const float*)d_in[1];
    const float* Wk = (const float*)d_in[2];
    const float* Wv = (const float*)d_in[3];
    const float* Wo = (const float*)d_in[4];
    float* out = (float*)d_out;

    void *pq, *pk, *pv;
    void *px1, *px2, *pa1, *pa2;
    void *pwq1, *pwq2, *pwk1, *pwk2, *pwv1, *pwv2, *pwo1, *pwo2;
    cudaGetSymbolAddress(&pq,  g_q);
    cudaGetSymbolAddress(&pk,  g_k);
    cudaGetSymbolAddress(&pv,  g_v);
    cudaGetSymbolAddress(&px1, g_x1);
    cudaGetSymbolAddress(&px2, g_x2);
    cudaGetSymbolAddress(&pa1, g_a1);
    cudaGetSymbolAddress(&pa2, g_a2);
    cudaGetSymbolAddress(&pwq1, g_wq1);
    cudaGetSymbolAddress(&pwq2, g_wq2);
    cudaGetSymbolAddress(&pwk1, g_wk1);
    cudaGetSymbolAddress(&pwk2, g_wk2);
    cudaGetSymbolAddress(&pwv1, g_wv1);
    cudaGetSymbolAddress(&pwv2, g_wv2);
    cudaGetSymbolAddress(&pwo1, g_wo1);
    cudaGetSymbolAddress(&pwo2, g_wo2);

    cudaFuncSetAttribute(mmah_gemm4<0>, cudaFuncAttributeMaxDynamicSharedMemorySize, MMA4_SMEM);
    cudaFuncSetAttribute(mmah_gemm4<1>, cudaFuncAttributeMaxDynamicSharedMemorySize, MMA4_SMEM);
    cudaFuncSetAttribute(mmah_gemm4<2>, cudaFuncAttributeMaxDynamicSharedMemorySize, MMA4_SMEM);
    cudaFuncSetAttribute(att_kernel, cudaFuncAttributeMaxDynamicSharedMemorySize,
                         (int)sizeof(AttSmem));

    zero_cnt<<<1, 1>>>();
    split_bf16<<<8192, 256>>>(x, (size_t)MROWS * DM,
                              (__nv_bfloat16*)px1, (__nv_bfloat16*)px2);
    split_bf16<<<1024, 256>>>(Wq, (size_t)DM * DM,
                              (__nv_bfloat16*)pwq1, (__nv_bfloat16*)pwq2);
    split_bf16<<<1024, 256>>>(Wk, (size_t)DM * DM,
                              (__nv_bfloat16*)pwk1, (__nv_bfloat16*)pwk2);
    split_bf16<<<1024, 256>>>(Wv, (size_t)DM * DM,
                              (__nv_bfloat16*)pwv1, (__nv_bfloat16*)pwv2);
    split_bf16<<<1024, 256>>>(Wo, (size_t)DM * DM,
                              (__nv_bfloat16*)pwo1, (__nv_bfloat16*)pwo2);

    dim3 grid(DM / 128, MROWS / 128), blk(256);
    // Q projection (scaled fp32 out)
    mmah_gemm4<1><<<grid, blk, MMA4_SMEM>>>(
        (const __nv_bfloat16*)px1, (const __nv_bfloat16*)px2,
        (const __nv_bfloat16*)pwq1, (const __nv_bfloat16*)pwq2, pq, 0u);
    // K/V sign projections on tensor cores + ambiguity candidates
    mmah_gemm4<2><<<grid, blk, MMA4_SMEM>>>(
        (const __nv_bfloat16*)px1, (const __nv_bfloat16*)px2,
        (const __nv_bfloat16*)pwk1, (const __nv_bfloat16*)pwk2, pk, 0u);
    mmah_gemm4<2><<<grid, blk, MMA4_SMEM>>>(
        (const __nv_bfloat16*)px1, (const __nv_bfloat16*)px2,
        (const __nv_bfloat16*)pwv1, (const __nv_bfloat16*)pwv2, pv, 1u);
    // exact-replay fixup (reproduces the validated fp32 signs bitwise)
    fixup<<<256, 256>>>(x, Wk, Wv);

    int write_state = ((size_t)out_size >= OUT_ELEMS + STATE_ELEMS) ? 1 : 0;
    att_kernel<<<128, 256, sizeof(AttSmem)>>>(
        (const float*)pq, (const int8_t*)pk, (const int8_t*)pv,
        (__nv_bfloat16*)pa1, (__nv_bfloat16*)pa2, out + OUT_ELEMS, write_state);

    mmah_gemm4<0><<<grid, blk, MMA4_SMEM>>>(
        (const __nv_bfloat16*)pa1, (const __nv_bfloat16*)pa2,
        (const __nv_bfloat16*)pwo1, (const __nv_bfloat16*)pwo2, out, 0u);
}

// round 13
// speedup vs baseline: 1.1484x; 1.1484x over previous
#include <cuda_runtime.h>
#include <cuda_bf16.h>
#include <cstdint>
#include <cstddef>

#define BSZ 4
#define SEQ 4096
#define DM  2048
#define NH  16
#define DH  128
#define MROWS (BSZ*SEQ)               // 16384
#define OUT_ELEMS ((size_t)MROWS*DM)  // 33554432
#define STATE_ELEMS ((size_t)BSZ*NH*DH*DH)
#define QSCALE 0.08838834764831845f   // 1/sqrt(128)
#define TAU 2.5e-4f                   // sign-ambiguity threshold
#define CAND_CAP 262144

typedef unsigned long long u64;

// ---------------- scratch (device globals: allocation-free rule) ------------
__device__ float  g_q [(size_t)MROWS*DM];
__device__ int8_t g_k [(size_t)MROWS*DM];
__device__ int8_t g_v [(size_t)MROWS*DM];
__device__ __nv_bfloat16 g_x1[(size_t)MROWS*DM];
__device__ __nv_bfloat16 g_x2[(size_t)MROWS*DM];
__device__ __nv_bfloat16 g_a1[(size_t)MROWS*DM];
__device__ __nv_bfloat16 g_a2[(size_t)MROWS*DM];
__device__ __nv_bfloat16 g_wq1[(size_t)DM*DM];
__device__ __nv_bfloat16 g_wq2[(size_t)DM*DM];
__device__ __nv_bfloat16 g_wk1[(size_t)DM*DM];
__device__ __nv_bfloat16 g_wk2[(size_t)DM*DM];
__device__ __nv_bfloat16 g_wv1[(size_t)DM*DM];
__device__ __nv_bfloat16 g_wv2[(size_t)DM*DM];
__device__ __nv_bfloat16 g_wo1[(size_t)DM*DM];
__device__ __nv_bfloat16 g_wo2[(size_t)DM*DM];
__device__ uint32_t g_cand[CAND_CAP];
__device__ uint32_t g_ncand;

// ---------------- mma.sync / ldmatrix / cp.async helpers --------------------
__device__ __forceinline__ uint32_t smem_u32(const void* p) {
    uint32_t a;
    asm("{ .reg .u64 t; cvta.to.shared.u64 t, %1; cvt.u32.u64 %0, t; }"
        : "=r"(a) : "l"(p));
    return a;
}
__device__ __forceinline__ void ldsm4(uint32_t* r, uint32_t addr) {
    asm volatile("ldmatrix.sync.aligned.m8n8.x4.shared.b16 {%0,%1,%2,%3}, [%4];"
        : "=r"(r[0]), "=r"(r[1]), "=r"(r[2]), "=r"(r[3]) : "r"(addr));
}
__device__ __forceinline__ void mma_bf16(float* c, const uint32_t* a,
                                         const uint32_t* b) {
    asm volatile(
        "mma.sync.aligned.m16n8k16.row.col.f32.bf16.bf16.f32 "
        "{%0,%1,%2,%3}, {%4,%5,%6,%7}, {%8,%9}, {%0,%1,%2,%3};"
        : "+f"(c[0]), "+f"(c[1]), "+f"(c[2]), "+f"(c[3])
        : "r"(a[0]), "r"(a[1]), "r"(a[2]), "r"(a[3]), "r"(b[0]), "r"(b[1]));
}
#define CPA(dst, src) asm volatile("cp.async.cg.shared.global [%0], [%1], 16;" :: "r"(dst), "l"(src))
#define CPC()         asm volatile("cp.async.commit_group;")
#define CPW0()        asm volatile("cp.async.wait_group 0;")

// ---------------------------------------------------------------------------
// split: fp32 -> bf16 hi + bf16 lo
// ---------------------------------------------------------------------------
__global__ void split_bf16(const float* __restrict__ s, size_t n,
                           __nv_bfloat16* __restrict__ hi,
                           __nv_bfloat16* __restrict__ lo)
{
    size_t stride = (size_t)gridDim.x * blockDim.x * 4;
    for (size_t i = ((size_t)blockIdx.x * blockDim.x + threadIdx.x) * 4;
         i < n; i += stride) {
        float4 v = *(const float4*)(s + i);
        __nv_bfloat16 hx = __float2bfloat16(v.x);
        __nv_bfloat16 hy = __float2bfloat16(v.y);
        __nv_bfloat16 hz = __float2bfloat16(v.z);
        __nv_bfloat16 hw = __float2bfloat16(v.w);
        __nv_bfloat16 lx = __float2bfloat16(v.x - __bfloat162float(hx));
        __nv_bfloat16 ly = __float2bfloat16(v.y - __bfloat162float(hy));
        __nv_bfloat16 lz = __float2bfloat16(v.z - __bfloat162float(hz));
        __nv_bfloat16 lw = __float2bfloat16(v.w - __bfloat162float(hw));
        *(__nv_bfloat162*)(hi + i)     = __nv_bfloat162(hx, hy);
        *(__nv_bfloat162*)(hi + i + 2) = __nv_bfloat162(hz, hw);
        *(__nv_bfloat162*)(lo + i)     = __nv_bfloat162(lx, ly);
        *(__nv_bfloat162*)(lo + i + 2) = __nv_bfloat162(lz, lw);
    }
}

__global__ void zero_cnt() { g_ncand = 0; }

// ---------------------------------------------------------------------------
// 2-split bf16 mma GEMM (NT), 2-stage pipeline, register-lean inner loop:
// B fragments loaded per-np and consumed immediately (live B regs 8, not 32)
// -> fits 128 regs -> __launch_bounds__(256,2) gives 2 blocks/SM.
// Per-accumulator MMA order unchanged (a1b1, a1b2, a2b1 per ks, k ascending)
// -> bit-identical to the validated R10 kernel.
// MODE 0: fp32 out.  MODE 1: fp32 out * QSCALE.
// MODE 2: int8 sign out + ambiguity candidates (|v| < TAU -> list).
// ---------------------------------------------------------------------------
#define RS   40
#define TILE_B (128 * RS * 2)          // 10240
#define BUF_B  (4 * TILE_B)            // 40960
#define MMA_SMEM (2 * BUF_B)           // 81920

template<int MODE>
__global__ void __launch_bounds__(256, 2)
mmah_gemm(const __nv_bfloat16* __restrict__ A1, const __nv_bfloat16* __restrict__ A2,
          const __nv_bfloat16* __restrict__ B1, const __nv_bfloat16* __restrict__ B2,
          void* __restrict__ Cv, uint32_t tag)
{
    extern __shared__ char sm[];
    const uint32_t smb = smem_u32(sm);
    const int tid = threadIdx.x, lane = tid & 31, w = tid >> 5;
    const int m0 = blockIdx.y * 128, n0 = blockIdx.x * 128;
    const int wm = (w & 3) * 32, wn = (w >> 2) * 64;

    const __nv_bfloat16* src[4] = {A1, A2, B1, B2};
    const int rbs[4] = {m0, m0, n0, n0};
    constexpr int NT = DM / 32;   // 64 stages

    auto issue = [&](int t) {
        const uint32_t bb = smb + (uint32_t)(t & 1) * BUF_B;
        const int k0 = t * 32;
#pragma unroll
        for (int i = 0; i < 2; i++) {
            const int c = tid + 256 * i;
            const int row = c >> 2, col8 = (c & 3) * 8;
#pragma unroll
            for (int X = 0; X < 4; X++) {
                uint32_t dst = bb + (uint32_t)X * TILE_B + row * (RS * 2) + col8 * 2;
                const __nv_bfloat16* s = src[X] + (size_t)(rbs[X] + row) * DM + k0 + col8;
                CPA(dst, s);
            }
        }
    };

    float acc[2][8][4];
#pragma unroll
    for (int mt = 0; mt < 2; mt++)
#pragma unroll
        for (int nt = 0; nt < 8; nt++)
#pragma unroll
            for (int e = 0; e < 4; e++) acc[mt][nt][e] = 0.f;

    issue(0); CPC();

    const int arow = wm + (lane & 15);
    const uint32_t acolo = ((lane >> 4) << 3) * 2;
    const int brow = wn + (lane & 7) + ((lane >> 4) << 3);
    const uint32_t bcolo = (((lane >> 3) & 1) << 3) * 2;

    for (int t = 0; t < NT; t++) {
        CPW0();
        __syncthreads();
        if (t + 1 < NT) { issue(t + 1); CPC(); }

        const uint32_t bb = smb + (uint32_t)(t & 1) * BUF_B;
#pragma unroll
        for (int ks = 0; ks < 32; ks += 16) {
            const uint32_t ko = (uint32_t)ks * 2;
            uint32_t a1f[2][4], a2f[2][4];
            ldsm4(a1f[0], bb + 0*TILE_B + (arow     ) * (RS*2) + ko + acolo);
            ldsm4(a1f[1], bb + 0*TILE_B + (arow + 16) * (RS*2) + ko + acolo);
            ldsm4(a2f[0], bb + 1*TILE_B + (arow     ) * (RS*2) + ko + acolo);
            ldsm4(a2f[1], bb + 1*TILE_B + (arow + 16) * (RS*2) + ko + acolo);
#pragma unroll
            for (int np = 0; np < 4; np++) {
                uint32_t r1[4], r2[4];
                ldsm4(r1, bb + 2*TILE_B + (brow + np*16) * (RS*2) + ko + bcolo);
                ldsm4(r2, bb + 3*TILE_B + (brow + np*16) * (RS*2) + ko + bcolo);
                // nt = np*2 uses {r[0],r[1]}; nt = np*2+1 uses {r[2],r[3]}
#pragma unroll
                for (int h = 0; h < 2; h++) {
                    const int nt = np * 2 + h;
                    uint32_t b1[2] = {r1[2*h], r1[2*h + 1]};
                    uint32_t b2[2] = {r2[2*h], r2[2*h + 1]};
#pragma unroll
                    for (int mt = 0; mt < 2; mt++) {
                        mma_bf16(acc[mt][nt], a1f[mt], b1);
                        mma_bf16(acc[mt][nt], a1f[mt], b2);
                        mma_bf16(acc[mt][nt], a2f[mt], b1);
                    }
                }
            }
        }
        __syncthreads();
    }

    if (MODE == 2) {
        int8_t* Cs = (int8_t*)Cv;
#pragma unroll
        for (int mt = 0; mt < 2; mt++)
#pragma unroll
            for (int nt = 0; nt < 8; nt++) {
                const int m = m0 + wm + mt * 16 + (lane >> 2);
                const int n = n0 + wn + nt * 8 + 2 * (lane & 3);
                const float* a = acc[mt][nt];
                char2 c01 = {(char)((a[0] >= 0.f) ? 1 : -1),
                             (char)((a[1] >= 0.f) ? 1 : -1)};
                char2 c23 = {(char)((a[2] >= 0.f) ? 1 : -1),
                             (char)((a[3] >= 0.f) ? 1 : -1)};
                *(char2*)&Cs[(size_t)m * DM + n]       = c01;
                *(char2*)&Cs[(size_t)(m + 8) * DM + n] = c23;
                const int mm[4] = {m, m, m + 8, m + 8};
                const int nn[4] = {n, n + 1, n, n + 1};
#pragma unroll
                for (int e = 0; e < 4; e++) {
                    if (fabsf(a[e]) < TAU) {
                        uint32_t idx = atomicAdd(&g_ncand, 1u);
                        if (idx < CAND_CAP)
                            g_cand[idx] = (tag << 25) |
                                          ((uint32_t)mm[e] << 11) | (uint32_t)nn[e];
                    }
                }
            }
    } else {
        float* C = (float*)Cv;
        const float s = (MODE == 1) ? QSCALE : 1.0f;
#pragma unroll
        for (int mt = 0; mt < 2; mt++)
#pragma unroll
            for (int nt = 0; nt < 8; nt++) {
                const int m = m0 + wm + mt * 16 + (lane >> 2);
                const int n = n0 + wn + nt * 8 + 2 * (lane & 3);
                float2 o0 = {acc[mt][nt][0] * s, acc[mt][nt][1] * s};
                float2 o1 = {acc[mt][nt][2] * s, acc[mt][nt][3] * s};
                *(float2*)&C[(size_t)m * DM + n]       = o0;
                *(float2*)&C[(size_t)(m + 8) * DM + n] = o1;
            }
    }
}

// ---------------------------------------------------------------------------
// Fixup: recompute each ambiguous element with the EXACT arithmetic of the
// validated fp32 gemm path: 32 segments of 64 sequential fmaf (k ascending),
// acc += segment. Signs bit-identical to the validated kernel.
// ---------------------------------------------------------------------------
__global__ void __launch_bounds__(256)
fixup(const float* __restrict__ x, const float* __restrict__ Wk,
      const float* __restrict__ Wv)
{
    uint32_t ncand = g_ncand;
    if (ncand > CAND_CAP) ncand = CAND_CAP;
    const uint32_t total = gridDim.x * blockDim.x;
    for (uint32_t i = blockIdx.x * blockDim.x + threadIdx.x; i < ncand;
         i += total) {
        const uint32_t c = g_cand[i];
        const int col = c & 2047;
        const int m   = (c >> 11) & 16383;
        const int tag = c >> 25;
        const float* a = x + (size_t)m * DM;
        const float* b = (tag ? Wv : Wk) + (size_t)col * DM;
        float acc = 0.f;
        for (int s = 0; s < 32; s++) {
            float tmp = 0.f;
            const float* as = a + s * 64;
            const float* bs = b + s * 64;
#pragma unroll
            for (int k4 = 0; k4 < 64; k4 += 4) {
                float4 av = *(const float4*)(as + k4);
                float4 bv = *(const float4*)(bs + k4);
                tmp = fmaf(av.x, bv.x, tmp);
                tmp = fmaf(av.y, bv.y, tmp);
                tmp = fmaf(av.z, bv.z, tmp);
                tmp = fmaf(av.w, bv.w, tmp);
            }
            acc += tmp;
        }
        int8_t* dst = tag ? g_v : g_k;
        dst[(size_t)m * DM + col] = (acc >= 0.f) ? (int8_t)1 : (int8_t)-1;
    }
}

// ---------------------------------------------------------------------------
// Attention scan (validated; epilogue writes bf16 2-split of output).
// ---------------------------------------------------------------------------
struct AttSmem {
    float  qcT[128][132];
    float  scoresT[128][132];
    float  state[128][68];
    int8_t kc[128][144];
    int8_t kT[128][144];
    int8_t vc[128][80];
};

__device__ __forceinline__ void b4_to_f(unsigned w, float* f) {
    f[0] = (float)((int)(w << 24) >> 24);
    f[1] = (float)((int)(w << 16) >> 24);
    f[2] = (float)((int)(w <<  8) >> 24);
    f[3] = (float)((int) w        >> 24);
}

__global__ void __launch_bounds__(256)
att_kernel(const float* __restrict__ gq, const int8_t* __restrict__ gk,
           const int8_t* __restrict__ gv,
           __nv_bfloat16* __restrict__ ga1, __nv_bfloat16* __restrict__ ga2,
           float* __restrict__ gstate, int write_state)
{
    extern __shared__ char sraw[];
    AttSmem& S = *(AttSmem*)sraw;

    const int pair = blockIdx.x;
    const int half = pair & 1;
    const int bh   = pair >> 1;
    const int b    = bh >> 4, h = bh & 15;
    const int tid  = threadIdx.x;

    for (int i = tid; i < 128 * 68; i += 256)
        ((float*)S.state)[i] = 0.f;

    const int ty = tid >> 4, tx = tid & 15;
    const int i0 = ty * 8, j0 = tx * 8, e0 = tx * 4;

    const size_t base_row = (size_t)b * SEQ;
    const int colq = h * DH;
    const int colv = h * DH + half * 64;

    const int lc = tid >> 1;
    const int dh = (tid & 1) * 64;

    for (int n = 0; n < 32; n++) {
        {
            const size_t row = base_row + (size_t)n * 128 + lc;
            const float* qs = gq + row * DM + colq + dh;
#pragma unroll
            for (int d4 = 0; d4 < 64; d4 += 4) {
                float4 v = *(const float4*)(qs + d4);
                S.qcT[dh + d4 + 0][lc] = v.x;
                S.qcT[dh + d4 + 1][lc] = v.y;
                S.qcT[dh + d4 + 2][lc] = v.z;
                S.qcT[dh + d4 + 3][lc] = v.w;
            }
            const int8_t* ks = gk + row * DM + colq + dh;
#pragma unroll
            for (int d16 = 0; d16 < 64; d16 += 16) {
                int4 kw = *(const int4*)(ks + d16);
                *(int4*)&S.kc[lc][dh + d16] = kw;
                const int8_t* kb = (const int8_t*)&kw;
#pragma unroll
                for (int z = 0; z < 16; z++)
                    S.kT[dh + d16 + z][lc] = kb[z];
            }
            const int8_t* vs = gv + row * DM + colv + (dh >> 1);
            *(int4*)&S.vc[lc][(dh >> 1) + 0]  = *(const int4*)(vs);
            *(int4*)&S.vc[lc][(dh >> 1) + 16] = *(const int4*)(vs + 16);
        }
        __syncthreads();

        float sc[8][8], cr[8][4];
#pragma unroll
        for (int i = 0; i < 8; i++) {
#pragma unroll
            for (int j = 0; j < 8; j++) sc[i][j] = 0.f;
#pragma unroll
            for (int e = 0; e < 4; e++) cr[i][e] = 0.f;
        }
        for (int kk = 0; kk < 128; kk++) {
            float4 q0 = *(const float4*)&S.qcT[kk][i0];
            float4 q1 = *(const float4*)&S.qcT[kk][i0 + 4];
            float qv[8] = {q0.x, q0.y, q0.z, q0.w, q1.x, q1.y, q1.z, q1.w};
            uint2 kw = *(const uint2*)&S.kT[kk][j0];
            float kf[8];
            b4_to_f(kw.x, kf); b4_to_f(kw.y, kf + 4);
            float4 st = *(const float4*)&S.state[kk][e0];
            float sf[4] = {st.x, st.y, st.z, st.w};
#pragma unroll
            for (int i = 0; i < 8; i++) {
#pragma unroll
                for (int j = 0; j < 8; j++)
                    sc[i][j] = fmaf(qv[i], kf[j], sc[i][j]);
#pragma unroll
                for (int e = 0; e < 4; e++)
                    cr[i][e] = fmaf(qv[i], sf[e], cr[i][e]);
            }
        }
#pragma unroll
        for (int jj = 0; jj < 8; jj++)
#pragma unroll
            for (int ii = 0; ii < 8; ii++) {
                int gi = i0 + ii, gj = j0 + jj;
                S.scoresT[gj][gi] = (gj <= gi) ? sc[ii][jj] : 0.f;
            }
        __syncthreads();

        float in8[8][4], up[8][4];
#pragma unroll
        for (int i = 0; i < 8; i++)
#pragma unroll
            for (int e = 0; e < 4; e++) { in8[i][e] = 0.f; up[i][e] = 0.f; }

        for (int kk = 0; kk < 128; kk++) {
            float4 s0 = *(const float4*)&S.scoresT[kk][i0];
            float4 s1 = *(const float4*)&S.scoresT[kk][i0 + 4];
            float sv[8] = {s0.x, s0.y, s0.z, s0.w, s1.x, s1.y, s1.z, s1.w};
            uint2 kw = *(const uint2*)&S.kc[kk][i0];
            float kf[8];
            b4_to_f(kw.x, kf); b4_to_f(kw.y, kf + 4);
            unsigned vw = *(const unsigned*)&S.vc[kk][e0];
            float vf[4];
            b4_to_f(vw, vf);
#pragma unroll
            for (int i = 0; i < 8; i++)
#pragma unroll
                for (int e = 0; e < 4; e++) {
                    in8[i][e] = fmaf(sv[i], vf[e], in8[i][e]);
                    up[i][e]  = fmaf(kf[i], vf[e], up[i][e]);
                }
        }
#pragma unroll
        for (int ii = 0; ii < 8; ii++) {
            size_t row = (base_row + (size_t)n * 128 + i0 + ii) * DM + colv + e0;
            float o[4] = {cr[ii][0] + in8[ii][0], cr[ii][1] + in8[ii][1],
                          cr[ii][2] + in8[ii][2], cr[ii][3] + in8[ii][3]};
            __nv_bfloat16 hb[4], lb[4];
#pragma unroll
            for (int e = 0; e < 4; e++) {
                hb[e] = __float2bfloat16(o[e]);
                lb[e] = __float2bfloat16(o[e] - __bfloat162float(hb[e]));
            }
            *(__nv_bfloat162*)(ga1 + row)     = __nv_bfloat162(hb[0], hb[1]);
            *(__nv_bfloat162*)(ga1 + row + 2) = __nv_bfloat162(hb[2], hb[3]);
            *(__nv_bfloat162*)(ga2 + row)     = __nv_bfloat162(lb[0], lb[1]);
            *(__nv_bfloat162*)(ga2 + row + 2) = __nv_bfloat162(lb[2], lb[3]);
#pragma unroll
            for (int e = 0; e < 4; e++)
                S.state[i0 + ii][e0 + e] += up[ii][e];
        }
        __syncthreads();
    }

    if (write_state) {
        for (int idx = tid; idx < 128 * 64; idx += 256) {
            int d = idx >> 6, e = idx & 63;
            gstate[(((size_t)(b * NH + h) * DH) + d) * DH + half * 64 + e]
                = S.state[d][e];
        }
    }
}

// ---------------------------------------------------------------------------
extern "C" void kernel_launch(void* const* d_in, const int* in_sizes, int n_in,
                              void* d_out, int out_size)
{
    const float* x  = (const float*)d_in[0];
    const float* Wq = (const float*)d_in[1];
    const float* Wk = (const float*)d_in[2];
    const float* Wv = (const float*)d_in[3];
    const float* Wo = (const float*)d_in[4];
    float* out = (float*)d_out;

    void *pq, *pk, *pv;
    void *px1, *px2, *pa1, *pa2;
    void *pwq1, *pwq2, *pwk1, *pwk2, *pwv1, *pwv2, *pwo1, *pwo2;
    cudaGetSymbolAddress(&pq,  g_q);
    cudaGetSymbolAddress(&pk,  g_k);
    cudaGetSymbolAddress(&pv,  g_v);
    cudaGetSymbolAddress(&px1, g_x1);
    cudaGetSymbolAddress(&px2, g_x2);
    cudaGetSymbolAddress(&pa1, g_a1);
    cudaGetSymbolAddress(&pa2, g_a2);
    cudaGetSymbolAddress(&pwq1, g_wq1);
    cudaGetSymbolAddress(&pwq2, g_wq2);
    cudaGetSymbolAddress(&pwk1, g_wk1);
    cudaGetSymbolAddress(&pwk2, g_wk2);
    cudaGetSymbolAddress(&pwv1, g_wv1);
    cudaGetSymbolAddress(&pwv2, g_wv2);
    cudaGetSymbolAddress(&pwo1, g_wo1);
    cudaGetSymbolAddress(&pwo2, g_wo2);

    cudaFuncSetAttribute(mmah_gemm<0>, cudaFuncAttributeMaxDynamicSharedMemorySize, MMA_SMEM);
    cudaFuncSetAttribute(mmah_gemm<1>, cudaFuncAttributeMaxDynamicSharedMemorySize, MMA_SMEM);
    cudaFuncSetAttribute(mmah_gemm<2>, cudaFuncAttributeMaxDynamicSharedMemorySize, MMA_SMEM);
    cudaFuncSetAttribute(att_kernel, cudaFuncAttributeMaxDynamicSharedMemorySize,
                         (int)sizeof(AttSmem));

    zero_cnt<<<1, 1>>>();
    split_bf16<<<8192, 256>>>(x, (size_t)MROWS * DM,
                              (__nv_bfloat16*)px1, (__nv_bfloat16*)px2);
    split_bf16<<<1024, 256>>>(Wq, (size_t)DM * DM,
                              (__nv_bfloat16*)pwq1, (__nv_bfloat16*)pwq2);
    split_bf16<<<1024, 256>>>(Wk, (size_t)DM * DM,
                              (__nv_bfloat16*)pwk1, (__nv_bfloat16*)pwk2);
    split_bf16<<<1024, 256>>>(Wv, (size_t)DM * DM,
                              (__nv_bfloat16*)pwv1, (__nv_bfloat16*)pwv2);
    split_bf16<<<1024, 256>>>(Wo, (size_t)DM * DM,
                              (__nv_bfloat16*)pwo1, (__nv_bfloat16*)pwo2);

    dim3 grid(DM / 128, MROWS / 128), blk(256);
    // Q projection (scaled fp32 out)
    mmah_gemm<1><<<grid, blk, MMA_SMEM>>>(
        (const __nv_bfloat16*)px1, (const __nv_bfloat16*)px2,
        (const __nv_bfloat16*)pwq1, (const __nv_bfloat16*)pwq2, pq, 0u);
    // K/V sign projections on tensor cores + ambiguity candidates
    mmah_gemm<2><<<grid, blk, MMA_SMEM>>>(
        (const __nv_bfloat16*)px1, (const __nv_bfloat16*)px2,
        (const __nv_bfloat16*)pwk1, (const __nv_bfloat16*)pwk2, pk, 0u);
    mmah_gemm<2><<<grid, blk, MMA_SMEM>>>(
        (const __nv_bfloat16*)px1, (const __nv_bfloat16*)px2,
        (const __nv_bfloat16*)pwv1, (const __nv_bfloat16*)pwv2, pv, 1u);
    // exact-replay fixup (reproduces the validated fp32 signs bitwise)
    fixup<<<256, 256>>>(x, Wk, Wv);

    int write_state = ((size_t)out_size >= OUT_ELEMS + STATE_ELEMS) ? 1 : 0;
    att_kernel<<<128, 256, sizeof(AttSmem)>>>(
        (const float*)pq, (const int8_t*)pk, (const int8_t*)pv,
        (__nv_bfloat16*)pa1, (__nv_bfloat16*)pa2, out + OUT_ELEMS, write_state);

    mmah_gemm<0><<<grid, blk, MMA_SMEM>>>(
        (const __nv_bfloat16*)pa1, (const __nv_bfloat16*)pa2,
        (const __nv_bfloat16*)pwo1, (const __nv_bfloat16*)pwo2, out, 0u);
}